// round 1
// baseline (speedup 1.0000x reference)
#include <cuda_runtime.h>
#include <cstdint>

// ---------------- problem constants ----------------
#define IN_DIM   57
#define HDIM     128
#define NCAT     18
#define SEQT     128
#define KX       64            // x-projection K padded 57 -> 64
#define KTOT     192           // KX + HDIM
#define KT       32            // k-tile streamed from L2
#define NTILES   6             // KTOT / KT
#define NGATE    512           // 4*H
#define MROWS    32            // batch rows per CTA
#define NBLOCKS  128           // 4096 / 32
#define NTHREADS 256
#define MPAD     36            // padded m-stride (144B, 16B aligned, kills STS conflicts)

#define W_FLOATS (2 * KT * NGATE)      // 32768 (two 64KB stages)
#define X_FLOATS (2 * KX * MPAD)       // 4608
#define H_FLOATS (2 * HDIM * MPAD)     // 9216
#define SMEM_BYTES ((W_FLOATS + X_FLOATS + H_FLOATS) * 4 + 16)

typedef unsigned long long u64;

// fused weight matrix [k][n] (k = 0..63 -> W_ih^T zero-padded, 64..191 -> W_hh^T)
__device__ __align__(128) float g_wcat[KTOT * NGATE];
__device__ __align__(128) float g_bias[NGATE];

// ---------------- small helpers ----------------
__device__ __forceinline__ uint32_t smem_u32(const void* p) {
    return (uint32_t)__cvta_generic_to_shared(p);
}
__device__ __forceinline__ u64 dup2(float x) {
    u64 d; asm("mov.b64 %0, {%1, %1};" : "=l"(d) : "f"(x)); return d;
}
__device__ __forceinline__ u64 pack2(float a, float b) {
    u64 d; asm("mov.b64 %0, {%1, %2};" : "=l"(d) : "f"(a), "f"(b)); return d;
}
__device__ __forceinline__ float2 unpk(u64 v) {
    float2 r; asm("mov.b64 {%0, %1}, %2;" : "=f"(r.x), "=f"(r.y) : "l"(v)); return r;
}
__device__ __forceinline__ void fma2(u64& d, u64 a, u64 b) {
    asm("fma.rn.f32x2 %0, %1, %2, %0;" : "+l"(d) : "l"(a), "l"(b));
}
__device__ __forceinline__ float ex2f(float x) {
    float y; asm("ex2.approx.f32 %0, %1;" : "=f"(y) : "f"(x)); return y;
}
__device__ __forceinline__ float rcpf(float x) {
    float y; asm("rcp.approx.f32 %0, %1;" : "=f"(y) : "f"(x)); return y;
}
__device__ __forceinline__ float sigf(float x) {
    return rcpf(1.0f + ex2f(-1.4426950408889634f * x));
}
__device__ __forceinline__ float tanhf_fast(float x) {
    float e = ex2f(2.8853900817779268f * x);     // e^{2x}
    return 1.0f - 2.0f * rcpf(e + 1.0f);
}
__device__ __forceinline__ void mbar_wait(uint32_t mbar, int phase) {
    asm volatile(
        "{\n\t.reg .pred P;\n\t"
        "LAB_WAIT_%=:\n\t"
        "mbarrier.try_wait.parity.acquire.cta.shared::cta.b64 P, [%0], %1, 0x989680;\n\t"
        "@P bra.uni LAB_DONE_%=;\n\t"
        "bra.uni LAB_WAIT_%=;\n\t"
        "LAB_DONE_%=:\n\t}"
        :: "r"(mbar), "r"(phase) : "memory");
}
__device__ __forceinline__ void issue_tile(uint32_t dst, const float* src,
                                           uint32_t mbar, int bytes) {
    asm volatile("mbarrier.arrive.expect_tx.shared.b64 _, [%0], %1;"
                 :: "r"(mbar), "r"(bytes) : "memory");
    asm volatile("cp.async.bulk.shared::cluster.global.mbarrier::complete_tx::bytes "
                 "[%0], [%1], %2, [%3];"
                 :: "r"(dst), "l"(src), "r"(bytes), "r"(mbar) : "memory");
}
// load x[:, tt, :] for this CTA's 32 rows, transposed to dst[k][m], zero-padded k>=57
__device__ __forceinline__ void load_x(const float* __restrict__ xin, int m0, int tt,
                                       float* dst, int tid) {
    int m  = tid >> 3;
    int kb = (tid & 7) * 8;
    const float* src = xin + ((size_t)(m0 + m) * SEQT + tt) * IN_DIM;
#pragma unroll
    for (int u = 0; u < 8; ++u) {
        int k = kb + u;
        dst[k * MPAD + m] = (k < IN_DIM) ? src[k] : 0.0f;
    }
}

// ---------------- prep: build fused weight + bias ----------------
__global__ void prep_kernel(const float* __restrict__ W_ih, const float* __restrict__ W_hh,
                            const float* __restrict__ b_ih, const float* __restrict__ b_hh) {
    int n = threadIdx.x;       // gate column 0..511
    int k = blockIdx.x;        // fused K row 0..191
    float v;
    if (k < KX) v = (k < IN_DIM) ? W_ih[n * IN_DIM + k] : 0.0f;
    else        v = W_hh[n * HDIM + (k - KX)];
    g_wcat[k * NGATE + n] = v;
    if (k == 0) g_bias[n] = b_ih[n] + b_hh[n];
}

// ---------------- persistent LSTM kernel ----------------
__global__ void __launch_bounds__(NTHREADS, 1)
lstm_kernel(const float* __restrict__ xin, const float* __restrict__ W_out,
            const float* __restrict__ b_out, float* __restrict__ out) {
    extern __shared__ float smem[];
    float* w_sh = smem;                       // [2][KT][512]
    float* x_sh = smem + W_FLOATS;            // [2][KX][MPAD]
    float* h_sh = x_sh + X_FLOATS;            // [2][HDIM][MPAD]
    u64*   mbar = (u64*)(h_sh + H_FLOATS);    // 2 mbarriers

    const int tid = threadIdx.x;
    const int hg  = tid & 63;                 // h-column pair index (hcol = 2*hg, 2*hg+1)
    const int mg  = tid >> 6;                 // m-group of 8 rows
    const int m0  = blockIdx.x * MROWS;

    const uint32_t mbar_addr = smem_u32(mbar);
    const uint32_t w_addr    = smem_u32(w_sh);

    if (tid == 0) {
        asm volatile("mbarrier.init.shared.b64 [%0], 1;" :: "r"(mbar_addr)     : "memory");
        asm volatile("mbarrier.init.shared.b64 [%0], 1;" :: "r"(mbar_addr + 8) : "memory");
    }
    // h(0) = 0 (buffer 0), load x(0) into x buffer 0
    for (int i = tid; i < HDIM * MPAD; i += NTHREADS) h_sh[i] = 0.0f;
    load_x(xin, m0, 0, x_sh, tid);
    __syncthreads();

    // bias pairs per gate for this thread's two h-columns
    u64 bias2[4];
#pragma unroll
    for (int gg = 0; gg < 4; ++gg)
        bias2[gg] = pack2(g_bias[gg * HDIM + hg * 2], g_bias[gg * HDIM + hg * 2 + 1]);

    float c0[8], c1[8];
#pragma unroll
    for (int i = 0; i < 8; ++i) { c0[i] = 0.0f; c1[i] = 0.0f; }

    u64 acc[4][8];

    // prime pipeline: tiles 0 and 1
    if (tid == 0) {
        issue_tile(w_addr,                    g_wcat,              mbar_addr,     KT * NGATE * 4);
        issue_tile(w_addr + KT * NGATE * 4,   g_wcat + KT * NGATE, mbar_addr + 8, KT * NGATE * 4);
    }

    int ph0 = 0, ph1 = 0;
    int t = 0, j = 0, jn = 2;

    for (int g = 0; g < SEQT * NTILES; ++g) {
        const int s = g & 1;
        if (s == 0) { mbar_wait(mbar_addr,     ph0); ph0 ^= 1; }
        else        { mbar_wait(mbar_addr + 8, ph1); ph1 ^= 1; }

        if (j == 0) {
#pragma unroll
            for (int gg = 0; gg < 4; ++gg)
#pragma unroll
                for (int mi = 0; mi < 8; ++mi) acc[gg][mi] = bias2[gg];
        }

        const float* wb = w_sh + s * (KT * NGATE) + hg * 2;
        const float* ab = (j < 2)
            ? (x_sh + (t & 1) * (KX * MPAD)   + j       * (KT * MPAD))
            : (h_sh + (t & 1) * (HDIM * MPAD) + (j - 2) * (KT * MPAD));
        ab += mg * 8;

#pragma unroll 8
        for (int kk = 0; kk < KT; ++kk) {
            float4 a0 = *(const float4*)(ab + kk * MPAD);       // broadcast within warp
            float4 a1 = *(const float4*)(ab + kk * MPAD + 4);
            u64 ad[8];
            ad[0] = dup2(a0.x); ad[1] = dup2(a0.y); ad[2] = dup2(a0.z); ad[3] = dup2(a0.w);
            ad[4] = dup2(a1.x); ad[5] = dup2(a1.y); ad[6] = dup2(a1.z); ad[7] = dup2(a1.w);
            const float* wr = wb + kk * NGATE;
            u64 wv[4];
            wv[0] = *(const u64*)(wr);
            wv[1] = *(const u64*)(wr + 128);
            wv[2] = *(const u64*)(wr + 256);
            wv[3] = *(const u64*)(wr + 384);
#pragma unroll
            for (int gg = 0; gg < 4; ++gg)
#pragma unroll
                for (int mi = 0; mi < 8; ++mi)
                    fma2(acc[gg][mi], ad[mi], wv[gg]);
        }

        // prefetch next step's x while W streaming continues
        if (j == 0 && t + 1 < SEQT)
            load_x(xin, m0, t + 1, x_sh + ((t + 1) & 1) * (KX * MPAD), tid);

        if (j == NTILES - 1) {
            // ---- per-step epilogue: activations + c/h update (all in registers) ----
            float* hout = h_sh + ((t + 1) & 1) * (HDIM * MPAD) + mg * 8;
#pragma unroll
            for (int mi = 0; mi < 8; ++mi) {
                float2 iv = unpk(acc[0][mi]);
                float2 fv = unpk(acc[1][mi]);
                float2 gv = unpk(acc[2][mi]);
                float2 ov = unpk(acc[3][mi]);
                float i0 = sigf(iv.x), f0 = sigf(fv.x), g0 = tanhf_fast(gv.x), o0 = sigf(ov.x);
                c0[mi] = f0 * c0[mi] + i0 * g0;
                hout[(hg * 2    ) * MPAD + mi] = o0 * tanhf_fast(c0[mi]);
                float i1 = sigf(iv.y), f1 = sigf(fv.y), g1 = tanhf_fast(gv.y), o1 = sigf(ov.y);
                c1[mi] = f1 * c1[mi] + i1 * g1;
                hout[(hg * 2 + 1) * MPAD + mi] = o1 * tanhf_fast(c1[mi]);
            }
        }

        __syncthreads();   // stage s fully consumed; h/x buffers published

        if (tid == 0 && g + 2 < SEQT * NTILES)
            issue_tile(w_addr + s * (KT * NGATE * 4),
                       g_wcat + jn * (KT * NGATE),
                       mbar_addr + s * 8, KT * NGATE * 4);
        jn = (jn + 1 == NTILES) ? 0 : jn + 1;
        if (j == NTILES - 1) { j = 0; ++t; } else ++j;
    }

    // ---- final Linear: out[m] = h_T @ W_out^T + b_out ----
    const float* hfin = h_sh;   // SEQT even -> final h in buffer 0
    for (int idx = tid; idx < MROWS * NCAT; idx += NTHREADS) {
        int mm  = idx / NCAT;
        int cat = idx - mm * NCAT;
        float sacc = b_out[cat];
        const float* wr = W_out + cat * HDIM;
#pragma unroll 8
        for (int k = 0; k < HDIM; ++k)
            sacc += hfin[k * MPAD + mm] * wr[k];
        out[(size_t)(m0 + mm) * NCAT + cat] = sacc;
    }
}

// ---------------- launch ----------------
extern "C" void kernel_launch(void* const* d_in, const int* in_sizes, int n_in,
                              void* d_out, int out_size) {
    const float* x     = (const float*)d_in[0];
    const float* W_ih  = (const float*)d_in[1];
    const float* W_hh  = (const float*)d_in[2];
    const float* b_ih  = (const float*)d_in[3];
    const float* b_hh  = (const float*)d_in[4];
    const float* W_out = (const float*)d_in[5];
    const float* b_out = (const float*)d_in[6];
    float* out = (float*)d_out;

    cudaFuncSetAttribute(lstm_kernel, cudaFuncAttributeMaxDynamicSharedMemorySize, SMEM_BYTES);

    prep_kernel<<<KTOT, NGATE>>>(W_ih, W_hh, b_ih, b_hh);
    lstm_kernel<<<NBLOCKS, NTHREADS, SMEM_BYTES>>>(x, W_out, b_out, out);
}